// round 2
// baseline (speedup 1.0000x reference)
#include <cuda_runtime.h>
#include <cuda_bf16.h>
#include <stdint.h>

#define NB 32
#define NS 2048
#define NH 1024
#define MTOT (NB*NS)     // 65536 flattened (s,b) rows
#define NTILES 8         // 1024 / 128

// scratch (static __device__ — no allocations allowed)
__device__ float g_hidc[NB*NH];          // hidden @ W1^T + bias   [b][h]
__device__ float g_part[NTILES*MTOT];    // per-N-tile partial scores

__device__ __forceinline__ uint32_t smem_u32(const void* p){
    return (uint32_t)__cvta_generic_to_shared(p);
}
__device__ __forceinline__ void ldsm4(uint32_t r[4], uint32_t addr){
    asm volatile("ldmatrix.sync.aligned.m8n8.x4.shared.b16 {%0,%1,%2,%3}, [%4];\n"
        : "=r"(r[0]),"=r"(r[1]),"=r"(r[2]),"=r"(r[3]) : "r"(addr));
}
__device__ __forceinline__ void mma16816(float c[4], const uint32_t a[4], uint32_t b0, uint32_t b1){
    asm volatile("mma.sync.aligned.m16n8k16.row.col.f32.bf16.bf16.f32 "
        "{%0,%1,%2,%3}, {%4,%5,%6,%7}, {%8,%9}, {%0,%1,%2,%3};\n"
        : "+f"(c[0]),"+f"(c[1]),"+f"(c[2]),"+f"(c[3])
        : "r"(a[0]),"r"(a[1]),"r"(a[2]),"r"(a[3]),"r"(b0),"r"(b1));
}

// ---------------------------------------------------------------------------
// K1: hidc[b][h] = sum_k hidden[b][k] * attn_W[h][k]  + attn_b[h]
// grid 128 x 256 threads, one thread per output.
// ---------------------------------------------------------------------------
__global__ void hidc_kernel(const float* __restrict__ hidden,
                            const float* __restrict__ W,
                            const float* __restrict__ bias){
    int idx = blockIdx.x * 256 + threadIdx.x;      // 0..32767
    int b = idx >> 10, h = idx & 1023;
    const float4* hr = (const float4*)(hidden + (size_t)b * NH);
    const float4* wr = (const float4*)(W + (size_t)h * (2*NH));
    float acc = 0.f;
    #pragma unroll 4
    for (int k = 0; k < NH/4; k++){
        float4 a = hr[k], w = wr[k];
        acc += a.x*w.x + a.y*w.y + a.z*w.z + a.w*w.w;
    }
    g_hidc[idx] = acc + bias[h];
}

// ---------------------------------------------------------------------------
// K2: per (mtile, ntile):  C = enc_tile @ W2_tile^T  (bf16x3 split precision),
// then partial_score[m] = sum_{n in tile} tanh(C + hidc[b][n]) * v[n].
// CTA tile 128x128, K=1024 in 32-wide blocks. 8 warps: 2(m) x 4(n),
// warp tile 64x32 with m16n8k16 mma.
// grid = (8 ntiles [x fastest -> A reuse in L2], 512 mtiles), 256 threads.
// ---------------------------------------------------------------------------
__global__ void __launch_bounds__(256)
gemm_scores_kernel(const float* __restrict__ enc,
                   const float* __restrict__ W,
                   const float* __restrict__ vW){
    __shared__ __nv_bfloat16 sAhi[128][40];
    __shared__ __nv_bfloat16 sAlo[128][40];
    __shared__ __nv_bfloat16 sBhi[128][40];
    __shared__ __nv_bfloat16 sBlo[128][40];
    __shared__ float s_row[128][4];

    const int tid  = threadIdx.x;
    const int lane = tid & 31, wid = tid >> 5;
    const int wm = wid & 1, wn = wid >> 1;
    const int mbase = wm * 64, nbase = wn * 32;
    const int g = lane >> 2, t = lane & 3;
    const int ntile = blockIdx.x, mtile = blockIdx.y;
    const int m0 = mtile * 128, n0 = ntile * 128;

    float c[4][4][4];
    #pragma unroll
    for (int i = 0; i < 4; i++)
        #pragma unroll
        for (int j = 0; j < 4; j++)
            #pragma unroll
            for (int k = 0; k < 4; k++) c[i][j][k] = 0.f;

    const float* Ag = enc + (size_t)m0 * NH;                 // rows: flattened (s,b)
    const float* Bg = W + (size_t)n0 * (2*NH) + NH;          // W2 = attn_W[:, H:2H]

    for (int kb = 0; kb < NH/32; ++kb){
        const int k0 = kb * 32;
        float4 va[4], vb[4];
        #pragma unroll
        for (int i = 0; i < 4; i++){
            int li = tid + i*256; int row = li >> 3; int c4 = li & 7;
            va[i] = *(const float4*)(Ag + (size_t)row * NH     + k0 + c4*4);
            vb[i] = *(const float4*)(Bg + (size_t)row * (2*NH) + k0 + c4*4);
        }
        __syncthreads();   // previous iteration's mma done reading smem
        #pragma unroll
        for (int i = 0; i < 4; i++){
            int li = tid + i*256; int row = li >> 3; int c4 = (li & 7) * 4;
            // A hi/lo
            __nv_bfloat162 h0 = __floats2bfloat162_rn(va[i].x, va[i].y);
            __nv_bfloat162 h1 = __floats2bfloat162_rn(va[i].z, va[i].w);
            __nv_bfloat162 l0 = __floats2bfloat162_rn(va[i].x - __low2float(h0),
                                                      va[i].y - __high2float(h0));
            __nv_bfloat162 l1 = __floats2bfloat162_rn(va[i].z - __low2float(h1),
                                                      va[i].w - __high2float(h1));
            *(__nv_bfloat162*)&sAhi[row][c4]   = h0;
            *(__nv_bfloat162*)&sAhi[row][c4+2] = h1;
            *(__nv_bfloat162*)&sAlo[row][c4]   = l0;
            *(__nv_bfloat162*)&sAlo[row][c4+2] = l1;
            // B hi/lo
            __nv_bfloat162 bh0 = __floats2bfloat162_rn(vb[i].x, vb[i].y);
            __nv_bfloat162 bh1 = __floats2bfloat162_rn(vb[i].z, vb[i].w);
            __nv_bfloat162 bl0 = __floats2bfloat162_rn(vb[i].x - __low2float(bh0),
                                                       vb[i].y - __high2float(bh0));
            __nv_bfloat162 bl1 = __floats2bfloat162_rn(vb[i].z - __low2float(bh1),
                                                       vb[i].w - __high2float(bh1));
            *(__nv_bfloat162*)&sBhi[row][c4]   = bh0;
            *(__nv_bfloat162*)&sBhi[row][c4+2] = bh1;
            *(__nv_bfloat162*)&sBlo[row][c4]   = bl0;
            *(__nv_bfloat162*)&sBlo[row][c4+2] = bl1;
        }
        __syncthreads();

        #pragma unroll
        for (int ks = 0; ks < 2; ++ks){
            const int r  = lane & 15;
            const int ch = ((lane >> 4) * 8) + ks * 16;
            uint32_t ah[4][4], al[4][4], bh[2][4], bl[2][4];
            #pragma unroll
            for (int mf = 0; mf < 4; mf++){
                ldsm4(ah[mf], smem_u32(&sAhi[mbase + mf*16 + r][ch]));
                ldsm4(al[mf], smem_u32(&sAlo[mbase + mf*16 + r][ch]));
            }
            #pragma unroll
            for (int nq = 0; nq < 2; nq++){
                ldsm4(bh[nq], smem_u32(&sBhi[nbase + nq*16 + r][ch]));
                ldsm4(bl[nq], smem_u32(&sBlo[nbase + nq*16 + r][ch]));
            }
            #pragma unroll
            for (int mf = 0; mf < 4; mf++){
                #pragma unroll
                for (int nf = 0; nf < 4; nf++){
                    const int nq = nf >> 1, hi = nf & 1;
                    mma16816(c[mf][nf], ah[mf], bh[nq][hi], bh[nq][hi+2]);
                    mma16816(c[mf][nf], ah[mf], bl[nq][hi], bl[nq][hi+2]);
                    mma16816(c[mf][nf], al[mf], bh[nq][hi], bh[nq][hi+2]);
                }
            }
        }
    }

    // Epilogue: partial scores. b = global_row % 32 (m0 divisible by 32).
    float rs0[4] = {0,0,0,0}, rs1[4] = {0,0,0,0};
    #pragma unroll
    for (int mf = 0; mf < 4; mf++){
        const int mlo = mbase + mf*16 + g;
        const int blo = mlo & 31;
        const int bhi = (mlo + 8) & 31;
        #pragma unroll
        for (int nf = 0; nf < 4; nf++){
            const int ngl = n0 + nbase + nf*8 + 2*t;
            float v0 = __ldg(&vW[ngl]), v1 = __ldg(&vW[ngl+1]);
            float h00 = g_hidc[blo*NH + ngl], h01 = g_hidc[blo*NH + ngl + 1];
            float h10 = g_hidc[bhi*NH + ngl], h11 = g_hidc[bhi*NH + ngl + 1];
            rs0[mf] += tanhf(c[mf][nf][0] + h00) * v0 + tanhf(c[mf][nf][1] + h01) * v1;
            rs1[mf] += tanhf(c[mf][nf][2] + h10) * v0 + tanhf(c[mf][nf][3] + h11) * v1;
        }
    }
    #pragma unroll
    for (int mf = 0; mf < 4; mf++){
        rs0[mf] += __shfl_xor_sync(0xffffffffu, rs0[mf], 1);
        rs0[mf] += __shfl_xor_sync(0xffffffffu, rs0[mf], 2);
        rs1[mf] += __shfl_xor_sync(0xffffffffu, rs1[mf], 1);
        rs1[mf] += __shfl_xor_sync(0xffffffffu, rs1[mf], 2);
    }
    if (t == 0){
        #pragma unroll
        for (int mf = 0; mf < 4; mf++){
            s_row[mbase + mf*16 + g    ][wn] = rs0[mf];
            s_row[mbase + mf*16 + g + 8][wn] = rs1[mf];
        }
    }
    __syncthreads();
    if (tid < 128){
        float s = s_row[tid][0] + s_row[tid][1] + s_row[tid][2] + s_row[tid][3];
        g_part[(size_t)ntile * MTOT + m0 + tid] = s;
    }
}

// ---------------------------------------------------------------------------
// K3: scores[b][s] = sum_nt g_part ; softmax over s ; write attn_weights
// one block per b (32 blocks, 256 threads)
// ---------------------------------------------------------------------------
__global__ void softmax_kernel(float* __restrict__ w_out){
    __shared__ float sc[NS];
    __shared__ float red[256];
    const int b = blockIdx.x, tid = threadIdx.x;

    float lmax = -1e30f;
    for (int s = tid; s < NS; s += 256){
        float v = 0.f;
        #pragma unroll
        for (int nt = 0; nt < NTILES; nt++)
            v += g_part[(size_t)nt * MTOT + s*NB + b];
        sc[s] = v;
        lmax = fmaxf(lmax, v);
    }
    red[tid] = lmax; __syncthreads();
    for (int o = 128; o > 0; o >>= 1){
        if (tid < o) red[tid] = fmaxf(red[tid], red[tid + o]);
        __syncthreads();
    }
    const float mx = red[0];
    __syncthreads();

    float lsum = 0.f;
    for (int s = tid; s < NS; s += 256){
        float e = expf(sc[s] - mx);
        sc[s] = e;
        lsum += e;
    }
    red[tid] = lsum; __syncthreads();
    for (int o = 128; o > 0; o >>= 1){
        if (tid < o) red[tid] = red[tid] + red[tid + o];
        __syncthreads();
    }
    const float inv = 1.f / red[0];
    for (int s = tid; s < NS; s += 256)
        w_out[b*NS + s] = sc[s] * inv;
}

// ---------------------------------------------------------------------------
// K4: context[b][h] = sum_s w[b][s] * enc[s][b][h]
// grid (8 hchunks, 32 b), 128 threads
// ---------------------------------------------------------------------------
__global__ void context_kernel(const float* __restrict__ enc,
                               const float* __restrict__ w,
                               float* __restrict__ ctx){
    const int b = blockIdx.y;
    const int h = blockIdx.x * 128 + threadIdx.x;
    const float* e  = enc + (size_t)b * NH + h;
    const float* wb = w + (size_t)b * NS;
    float acc = 0.f;
    for (int s = 0; s < NS; s += 8){
        #pragma unroll
        for (int j = 0; j < 8; j++)
            acc += wb[s + j] * e[(size_t)(s + j) * (NB*NH)];
    }
    ctx[(size_t)b * NH + h] = acc;
}

// ---------------------------------------------------------------------------
extern "C" void kernel_launch(void* const* d_in, const int* in_sizes, int n_in,
                              void* d_out, int out_size){
    const float* hidden = (const float*)d_in[0];   // [B,H]
    const float* enc    = (const float*)d_in[1];   // [S,B,H]
    const float* attn_W = (const float*)d_in[2];   // [H,2H]
    const float* attn_b = (const float*)d_in[3];   // [H]
    const float* v_W    = (const float*)d_in[4];   // [1,H]
    float* out = (float*)d_out;
    float* ctx = out;                 // [B,H]
    float* wts = out + NB*NH;         // [B,S]

    hidc_kernel<<<128, 256>>>(hidden, attn_W, attn_b);
    gemm_scores_kernel<<<dim3(NTILES, MTOT/128), 256>>>(enc, attn_W, v_W);
    softmax_kernel<<<NB, 256>>>(wts);
    context_kernel<<<dim3(NH/128, NB), 128>>>(enc, wts, ctx);
}

// round 6
// speedup vs baseline: 1.1483x; 1.1483x over previous
#include <cuda_runtime.h>
#include <cuda_bf16.h>
#include <stdint.h>

#define NB 32
#define NS 2048
#define NH 1024
#define MTOT (NB*NS)      // 65536 flattened (s,b) rows
#define NTILES 8          // NH / 128
#define KCH 64            // k-chunk in elements (128 B per row in bf16)
#define NCHUNK (NH/KCH)   // 16

// smem buffer layout (per pipeline stage): A hi/lo 16KB each, B hi/lo 16KB each
#define SA_HI 0
#define SA_LO 16384
#define SB_HI 32768
#define SB_LO 49152
#define BUFSZ 65536
#define SROW_OFF (2*BUFSZ)            // 128*4 floats
#define SMEM_TOTAL (2*BUFSZ + 2048)

// persistent scratch (static __device__ — no allocations allowed)
__device__ float g_hidc[NB*NH];
__device__ float g_part[NTILES*MTOT];
__device__ __align__(16) __nv_bfloat16 g_encH[MTOT*NH];   // 134 MB
__device__ __align__(16) __nv_bfloat16 g_encL[MTOT*NH];   // 134 MB
__device__ __align__(16) __nv_bfloat16 g_w2H[NH*NH];      // 2 MB
__device__ __align__(16) __nv_bfloat16 g_w2L[NH*NH];      // 2 MB

// ---------------- helpers ----------------
__device__ __forceinline__ uint32_t smem_u32(const void* p){
    uint32_t a;
    asm("{ .reg .u64 t; cvta.to.shared.u64 t, %1; cvt.u32.u64 %0, t; }" : "=r"(a) : "l"(p));
    return a;
}
__device__ __forceinline__ void cp16(uint32_t dst, const void* src){
    asm volatile("cp.async.cg.shared.global [%0], [%1], 16;" :: "r"(dst), "l"(src));
}
__device__ __forceinline__ void cp_commit(){
    asm volatile("cp.async.commit_group;");
}
template<int N> __device__ __forceinline__ void cp_wait(){
    asm volatile("cp.async.wait_group %0;" :: "n"(N));
}
__device__ __forceinline__ void ldsm4(uint32_t r[4], uint32_t addr){
    asm volatile("ldmatrix.sync.aligned.m8n8.x4.shared.b16 {%0,%1,%2,%3}, [%4];\n"
        : "=r"(r[0]),"=r"(r[1]),"=r"(r[2]),"=r"(r[3]) : "r"(addr));
}
__device__ __forceinline__ void mma16816(float c[4], const uint32_t a[4], uint32_t b0, uint32_t b1){
    asm volatile("mma.sync.aligned.m16n8k16.row.col.f32.bf16.bf16.f32 "
        "{%0,%1,%2,%3}, {%4,%5,%6,%7}, {%8,%9}, {%0,%1,%2,%3};\n"
        : "+f"(c[0]),"+f"(c[1]),"+f"(c[2]),"+f"(c[3])
        : "r"(a[0]),"r"(a[1]),"r"(a[2]),"r"(a[3]),"r"(b0),"r"(b1));
}
__device__ __forceinline__ uint32_t b2u(__nv_bfloat162 v){ return *reinterpret_cast<uint32_t*>(&v); }

// ---------------------------------------------------------------------------
// K0a: convert enc fp32 -> bf16 hi/lo (8 elems per thread)
// ---------------------------------------------------------------------------
__global__ void cvt_enc_kernel(const float* __restrict__ enc){
    size_t base = ((size_t)blockIdx.x * 256 + threadIdx.x) * 8;
    float4 v0 = *(const float4*)(enc + base);
    float4 v1 = *(const float4*)(enc + base + 4);
    __nv_bfloat162 h0 = __floats2bfloat162_rn(v0.x, v0.y);
    __nv_bfloat162 h1 = __floats2bfloat162_rn(v0.z, v0.w);
    __nv_bfloat162 h2 = __floats2bfloat162_rn(v1.x, v1.y);
    __nv_bfloat162 h3 = __floats2bfloat162_rn(v1.z, v1.w);
    __nv_bfloat162 l0 = __floats2bfloat162_rn(v0.x - __low2float(h0), v0.y - __high2float(h0));
    __nv_bfloat162 l1 = __floats2bfloat162_rn(v0.z - __low2float(h1), v0.w - __high2float(h1));
    __nv_bfloat162 l2 = __floats2bfloat162_rn(v1.x - __low2float(h2), v1.y - __high2float(h2));
    __nv_bfloat162 l3 = __floats2bfloat162_rn(v1.z - __low2float(h3), v1.w - __high2float(h3));
    *(uint4*)(g_encH + base) = make_uint4(b2u(h0), b2u(h1), b2u(h2), b2u(h3));
    *(uint4*)(g_encL + base) = make_uint4(b2u(l0), b2u(l1), b2u(l2), b2u(l3));
}

// ---------------------------------------------------------------------------
// K0b: convert W2 = attn_W[:, H:2H] -> bf16 hi/lo  [n][k] row-major
// ---------------------------------------------------------------------------
__global__ void cvt_w2_kernel(const float* __restrict__ W){
    size_t idx = ((size_t)blockIdx.x * 256 + threadIdx.x) * 8;   // over NH*NH
    int n = (int)(idx >> 10), k = (int)(idx & 1023);
    const float* src = W + (size_t)n * (2*NH) + NH + k;
    float4 v0 = *(const float4*)(src);
    float4 v1 = *(const float4*)(src + 4);
    __nv_bfloat162 h0 = __floats2bfloat162_rn(v0.x, v0.y);
    __nv_bfloat162 h1 = __floats2bfloat162_rn(v0.z, v0.w);
    __nv_bfloat162 h2 = __floats2bfloat162_rn(v1.x, v1.y);
    __nv_bfloat162 h3 = __floats2bfloat162_rn(v1.z, v1.w);
    __nv_bfloat162 l0 = __floats2bfloat162_rn(v0.x - __low2float(h0), v0.y - __high2float(h0));
    __nv_bfloat162 l1 = __floats2bfloat162_rn(v0.z - __low2float(h1), v0.w - __high2float(h1));
    __nv_bfloat162 l2 = __floats2bfloat162_rn(v1.x - __low2float(h2), v1.y - __high2float(h2));
    __nv_bfloat162 l3 = __floats2bfloat162_rn(v1.z - __low2float(h3), v1.w - __high2float(h3));
    *(uint4*)(g_w2H + idx) = make_uint4(b2u(h0), b2u(h1), b2u(h2), b2u(h3));
    *(uint4*)(g_w2L + idx) = make_uint4(b2u(l0), b2u(l1), b2u(l2), b2u(l3));
}

// ---------------------------------------------------------------------------
// K1: hidc[b][h] = hidden[b] . attn_W[h][0:H] + bias[h]
// ---------------------------------------------------------------------------
__global__ void hidc_kernel(const float* __restrict__ hidden,
                            const float* __restrict__ W,
                            const float* __restrict__ bias){
    int idx = blockIdx.x * 256 + threadIdx.x;
    int b = idx >> 10, h = idx & 1023;
    const float4* hr = (const float4*)(hidden + (size_t)b * NH);
    const float4* wr = (const float4*)(W + (size_t)h * (2*NH));
    float acc = 0.f;
    #pragma unroll 4
    for (int k = 0; k < NH/4; k++){
        float4 a = hr[k], w = wr[k];
        acc += a.x*w.x + a.y*w.y + a.z*w.z + a.w*w.w;
    }
    g_hidc[idx] = acc + bias[h];
}

// ---------------------------------------------------------------------------
// K2: pipelined mma.sync GEMM (bf16x3) + tanh + v-dot epilogue.
// CTA 128x128, 8 warps (2m x 4n), warp tile 64x32, k-chunk 64, double-buffered
// cp.async from pre-converted bf16 hi/lo arrays.
// grid (8 ntiles [x fastest -> A reuse in L2], 512 mtiles), 256 threads.
// ---------------------------------------------------------------------------
__global__ void __launch_bounds__(256, 1)
gemm_scores_mma(const float* __restrict__ vW){
    extern __shared__ char smem[];
    const uint32_t sb = smem_u32(smem);
    float (*s_row)[4] = (float(*)[4])(smem + SROW_OFF);

    const int tid  = threadIdx.x;
    const int lane = tid & 31, wid = tid >> 5;
    const int wm = wid & 1, wn = wid >> 1;
    const int mbase = wm * 64, nbase = wn * 32;
    const int g = lane >> 2, t = lane & 3;
    const int ntile = blockIdx.x, mtile = blockIdx.y;
    const int m0 = mtile * 128, n0 = ntile * 128;

    const __nv_bfloat16* AgH = g_encH + (size_t)m0 * NH;
    const __nv_bfloat16* AgL = g_encL + (size_t)m0 * NH;
    const __nv_bfloat16* BgH = g_w2H + (size_t)n0 * NH;
    const __nv_bfloat16* BgL = g_w2L + (size_t)n0 * NH;

    float c[4][4][4];
    #pragma unroll
    for (int i = 0; i < 4; i++)
        #pragma unroll
        for (int j = 0; j < 4; j++)
            #pragma unroll
            for (int k = 0; k < 4; k++) c[i][j][k] = 0.f;

    // prefetch lambda: chunk ci -> buffer buf
    auto prefetch = [&](int ci, int buf){
        const uint32_t so = sb + buf * BUFSZ;
        const int k0 = ci * KCH;
        #pragma unroll
        for (int i = 0; i < 4; i++){
            int u = i * 256 + tid;            // 0..1023
            int row = u >> 3, cu = u & 7;
            uint32_t rel = (uint32_t)(row * 128) + (((uint32_t)cu * 16) ^ (((uint32_t)row & 7) << 4));
            const size_t go = (size_t)row * NH + k0 + cu * 8;
            cp16(so + SA_HI + rel, AgH + go);
            cp16(so + SA_LO + rel, AgL + go);
            cp16(so + SB_HI + rel, BgH + go);
            cp16(so + SB_LO + rel, BgL + go);
        }
    };

    prefetch(0, 0); cp_commit();
    prefetch(1, 1); cp_commit();

    for (int ci = 0; ci < NCHUNK; ci++){
        cp_wait<1>();
        __syncthreads();
        const uint32_t so = sb + (ci & 1) * BUFSZ;
        #pragma unroll
        for (int ks = 0; ks < 4; ks++){
            const int r = lane & 15;
            const uint32_t colb = (uint32_t)(ks * 32 + (lane >> 4) * 16);
            uint32_t ah[4][4], al[4][4], bh[2][4], bl[2][4];
            #pragma unroll
            for (int mf = 0; mf < 4; mf++){
                const uint32_t row = (uint32_t)(mbase + mf * 16 + r);
                const uint32_t rel = row * 128 + (colb ^ ((row & 7) << 4));
                ldsm4(ah[mf], so + SA_HI + rel);
                ldsm4(al[mf], so + SA_LO + rel);
            }
            #pragma unroll
            for (int nq = 0; nq < 2; nq++){
                const uint32_t row = (uint32_t)(nbase + nq * 16 + r);
                const uint32_t rel = row * 128 + (colb ^ ((row & 7) << 4));
                ldsm4(bh[nq], so + SB_HI + rel);
                ldsm4(bl[nq], so + SB_LO + rel);
            }
            #pragma unroll
            for (int mf = 0; mf < 4; mf++){
                #pragma unroll
                for (int nf = 0; nf < 4; nf++){
                    const int nq = nf >> 1, hi = nf & 1;
                    mma16816(c[mf][nf], ah[mf], bh[nq][hi], bh[nq][hi+2]);
                    mma16816(c[mf][nf], ah[mf], bl[nq][hi], bl[nq][hi+2]);
                    mma16816(c[mf][nf], al[mf], bh[nq][hi], bh[nq][hi+2]);
                }
            }
        }
        __syncthreads();
        if (ci + 2 < NCHUNK) prefetch(ci + 2, ci & 1);
        cp_commit();
    }

    // Epilogue: partial scores. b = global_row % 32 (m0 divisible by 32).
    float rs0[4] = {0,0,0,0}, rs1[4] = {0,0,0,0};
    #pragma unroll
    for (int mf = 0; mf < 4; mf++){
        const int mlo = mbase + mf*16 + g;
        const int blo = mlo & 31;
        const int bhi = (mlo + 8) & 31;
        #pragma unroll
        for (int nf = 0; nf < 4; nf++){
            const int ngl = n0 + nbase + nf*8 + 2*t;
            float v0 = __ldg(&vW[ngl]), v1 = __ldg(&vW[ngl+1]);
            float h00 = g_hidc[blo*NH + ngl], h01 = g_hidc[blo*NH + ngl + 1];
            float h10 = g_hidc[bhi*NH + ngl], h11 = g_hidc[bhi*NH + ngl + 1];
            rs0[mf] += tanhf(c[mf][nf][0] + h00) * v0 + tanhf(c[mf][nf][1] + h01) * v1;
            rs1[mf] += tanhf(c[mf][nf][2] + h10) * v0 + tanhf(c[mf][nf][3] + h11) * v1;
        }
    }
    #pragma unroll
    for (int mf = 0; mf < 4; mf++){
        rs0[mf] += __shfl_xor_sync(0xffffffffu, rs0[mf], 1);
        rs0[mf] += __shfl_xor_sync(0xffffffffu, rs0[mf], 2);
        rs1[mf] += __shfl_xor_sync(0xffffffffu, rs1[mf], 1);
        rs1[mf] += __shfl_xor_sync(0xffffffffu, rs1[mf], 2);
    }
    __syncthreads();
    if (t == 0){
        #pragma unroll
        for (int mf = 0; mf < 4; mf++){
            s_row[mbase + mf*16 + g    ][wn] = rs0[mf];
            s_row[mbase + mf*16 + g + 8][wn] = rs1[mf];
        }
    }
    __syncthreads();
    if (tid < 128){
        float s = s_row[tid][0] + s_row[tid][1] + s_row[tid][2] + s_row[tid][3];
        g_part[(size_t)ntile * MTOT + m0 + tid] = s;
    }
}

// ---------------------------------------------------------------------------
// K3: sum partials -> softmax over S per batch -> attn_weights; zero ctx
// ---------------------------------------------------------------------------
__global__ void softmax_kernel(float* __restrict__ w_out, float* __restrict__ ctx){
    __shared__ float sc[NS];
    __shared__ float red[256];
    const int b = blockIdx.x, tid = threadIdx.x;

    #pragma unroll
    for (int i = tid; i < NH; i += 256) ctx[b * NH + i] = 0.f;

    float lmax = -1e30f;
    for (int s = tid; s < NS; s += 256){
        float v = 0.f;
        #pragma unroll
        for (int nt = 0; nt < NTILES; nt++)
            v += g_part[(size_t)nt * MTOT + s * NB + b];
        sc[s] = v;
        lmax = fmaxf(lmax, v);
    }
    red[tid] = lmax; __syncthreads();
    for (int o = 128; o > 0; o >>= 1){
        if (tid < o) red[tid] = fmaxf(red[tid], red[tid + o]);
        __syncthreads();
    }
    const float mx = red[0];
    __syncthreads();

    float lsum = 0.f;
    for (int s = tid; s < NS; s += 256){
        float e = expf(sc[s] - mx);
        sc[s] = e;
        lsum += e;
    }
    red[tid] = lsum; __syncthreads();
    for (int o = 128; o > 0; o >>= 1){
        if (tid < o) red[tid] = red[tid] + red[tid + o];
        __syncthreads();
    }
    const float inv = 1.f / red[0];
    for (int s = tid; s < NS; s += 256)
        w_out[b * NS + s] = sc[s] * inv;
}

// ---------------------------------------------------------------------------
// K4: context[b][h] += sum_{s in chunk} w[b][s] * enc[s][b][h]  (atomic)
// grid (8 hchunk, 32 b, 16 schunk), 128 threads
// ---------------------------------------------------------------------------
__global__ void context_kernel(const float* __restrict__ enc,
                               const float* __restrict__ w,
                               float* __restrict__ ctx){
    const int b = blockIdx.y;
    const int h = blockIdx.x * 128 + threadIdx.x;
    const int s0 = blockIdx.z * 128;
    const float* e  = enc + (size_t)s0 * (NB*NH) + (size_t)b * NH + h;
    const float* wb = w + (size_t)b * NS + s0;
    float acc = 0.f;
    #pragma unroll 8
    for (int j = 0; j < 128; j++)
        acc += wb[j] * e[(size_t)j * (NB*NH)];
    atomicAdd(&ctx[(size_t)b * NH + h], acc);
}

// ---------------------------------------------------------------------------
extern "C" void kernel_launch(void* const* d_in, const int* in_sizes, int n_in,
                              void* d_out, int out_size){
    const float* hidden = (const float*)d_in[0];   // [B,H]
    const float* enc    = (const float*)d_in[1];   // [S,B,H]
    const float* attn_W = (const float*)d_in[2];   // [H,2H]
    const float* attn_b = (const float*)d_in[3];   // [H]
    const float* v_W    = (const float*)d_in[4];   // [1,H]
    float* out = (float*)d_out;
    float* ctx = out;                 // [B,H]
    float* wts = out + NB*NH;         // [B,S]

    cudaFuncSetAttribute(gemm_scores_mma, cudaFuncAttributeMaxDynamicSharedMemorySize, SMEM_TOTAL);

    cvt_enc_kernel<<<(MTOT*(NH/8))/256, 256>>>(enc);        // 32768 blocks
    cvt_w2_kernel<<<(NH*(NH/8))/256, 256>>>(attn_W);        // 512 blocks
    hidc_kernel<<<128, 256>>>(hidden, attn_W, attn_b);
    gemm_scores_mma<<<dim3(NTILES, MTOT/128), 256, SMEM_TOTAL>>>(v_W);
    softmax_kernel<<<NB, 256>>>(wts, ctx);
    context_kernel<<<dim3(NH/128, NB, NS/128), 128>>>(enc, wts, ctx);
}

// round 7
// speedup vs baseline: 2.4881x; 2.1667x over previous
#include <cuda_runtime.h>
#include <cuda_fp16.h>
#include <stdint.h>

#define NB 32
#define NS 2048
#define NH 1024
#define MTOT (NB*NS)      // 65536 flattened (s,b) rows
#define NTILES 4          // NH / N_CTA
#define N_CTA 256
#define M_CTA 128
#define KCH 64            // k-chunk elems (128B rows in fp16)
#define NCHUNK (NH/KCH)   // 16
#define NSTAGE 3

// smem: per stage A 16KB + B 32KB
#define SB_OFF 16384
#define STAGESZ 49152
#define SROW_OFF (NSTAGE*STAGESZ)
#define SMEM_TOTAL (NSTAGE*STAGESZ + 2048)

// persistent scratch
__device__ float g_hidc[NB*NH];
__device__ float g_part[NTILES*MTOT];
__device__ __align__(16) __half g_encF[MTOT*NH];   // 134 MB
__device__ __align__(16) __half g_w2F[NH*NH];      // 2 MB

// ---------------- helpers ----------------
__device__ __forceinline__ uint32_t smem_u32(const void* p){
    uint32_t a;
    asm("{ .reg .u64 t; cvta.to.shared.u64 t, %1; cvt.u32.u64 %0, t; }" : "=r"(a) : "l"(p));
    return a;
}
__device__ __forceinline__ void cp16(uint32_t dst, const void* src){
    asm volatile("cp.async.cg.shared.global [%0], [%1], 16;" :: "r"(dst), "l"(src));
}
__device__ __forceinline__ void cp_commit(){
    asm volatile("cp.async.commit_group;");
}
template<int N> __device__ __forceinline__ void cp_wait(){
    asm volatile("cp.async.wait_group %0;" :: "n"(N));
}
__device__ __forceinline__ void ldsm4(uint32_t r[4], uint32_t addr){
    asm volatile("ldmatrix.sync.aligned.m8n8.x4.shared.b16 {%0,%1,%2,%3}, [%4];\n"
        : "=r"(r[0]),"=r"(r[1]),"=r"(r[2]),"=r"(r[3]) : "r"(addr));
}
__device__ __forceinline__ void mma16816(float c[4], const uint32_t a[4], uint32_t b0, uint32_t b1){
    asm volatile("mma.sync.aligned.m16n8k16.row.col.f32.f16.f16.f32 "
        "{%0,%1,%2,%3}, {%4,%5,%6,%7}, {%8,%9}, {%0,%1,%2,%3};\n"
        : "+f"(c[0]),"+f"(c[1]),"+f"(c[2]),"+f"(c[3])
        : "r"(a[0]),"r"(a[1]),"r"(a[2]),"r"(a[3]),"r"(b0),"r"(b1));
}
__device__ __forceinline__ uint32_t h2u(__half2 v){ return *reinterpret_cast<uint32_t*>(&v); }

// ---------------------------------------------------------------------------
// K0a: enc fp32 -> fp16  (8 elems / thread)
// ---------------------------------------------------------------------------
__global__ void cvt_enc_kernel(const float* __restrict__ enc){
    size_t base = ((size_t)blockIdx.x * 256 + threadIdx.x) * 8;
    float4 v0 = *(const float4*)(enc + base);
    float4 v1 = *(const float4*)(enc + base + 4);
    __half2 h0 = __floats2half2_rn(v0.x, v0.y);
    __half2 h1 = __floats2half2_rn(v0.z, v0.w);
    __half2 h2 = __floats2half2_rn(v1.x, v1.y);
    __half2 h3 = __floats2half2_rn(v1.z, v1.w);
    *(uint4*)(g_encF + base) = make_uint4(h2u(h0), h2u(h1), h2u(h2), h2u(h3));
}

// ---------------------------------------------------------------------------
// K0b: W2 = attn_W[:, H:2H] -> fp16  [n][k] row-major
// ---------------------------------------------------------------------------
__global__ void cvt_w2_kernel(const float* __restrict__ W){
    size_t idx = ((size_t)blockIdx.x * 256 + threadIdx.x) * 8;
    int n = (int)(idx >> 10), k = (int)(idx & 1023);
    const float* src = W + (size_t)n * (2*NH) + NH + k;
    float4 v0 = *(const float4*)(src);
    float4 v1 = *(const float4*)(src + 4);
    __half2 h0 = __floats2half2_rn(v0.x, v0.y);
    __half2 h1 = __floats2half2_rn(v0.z, v0.w);
    __half2 h2 = __floats2half2_rn(v1.x, v1.y);
    __half2 h3 = __floats2half2_rn(v1.z, v1.w);
    *(uint4*)(g_w2F + idx) = make_uint4(h2u(h0), h2u(h1), h2u(h2), h2u(h3));
}

// ---------------------------------------------------------------------------
// K1: hidc[b][h] = hidden[b] . attn_W[h][0:H] + bias[h]   (fp32 exact)
// ---------------------------------------------------------------------------
__global__ void hidc_kernel(const float* __restrict__ hidden,
                            const float* __restrict__ W,
                            const float* __restrict__ bias){
    int idx = blockIdx.x * 256 + threadIdx.x;
    int b = idx >> 10, h = idx & 1023;
    const float4* hr = (const float4*)(hidden + (size_t)b * NH);
    const float4* wr = (const float4*)(W + (size_t)h * (2*NH));
    float acc = 0.f;
    #pragma unroll 4
    for (int k = 0; k < NH/4; k++){
        float4 a = hr[k], w = wr[k];
        acc += a.x*w.x + a.y*w.y + a.z*w.z + a.w*w.w;
    }
    g_hidc[idx] = acc + bias[h];
}

// ---------------------------------------------------------------------------
// K2: fp16 single-pass mma.sync GEMM + tanh + v-dot epilogue.
// CTA 128x256, 8 warps (2m x 4n), warp tile 64x64, k-chunk 64, 3-stage cp.async.
// grid (4 ntiles [x fastest -> A reuse in L2], 512 mtiles), 256 threads.
// ---------------------------------------------------------------------------
__global__ void __launch_bounds__(256, 1)
gemm_scores_mma(const float* __restrict__ vW){
    extern __shared__ char smem[];
    const uint32_t sb = smem_u32(smem);
    float (*s_row)[4] = (float(*)[4])(smem + SROW_OFF);

    const int tid  = threadIdx.x;
    const int lane = tid & 31, wid = tid >> 5;
    const int wm = wid & 1, wn = wid >> 1;
    const int mbase = wm * 64, nbase = wn * 64;
    const int g = lane >> 2, t = lane & 3;
    const int ntile = blockIdx.x, mtile = blockIdx.y;
    const int m0 = mtile * M_CTA, n0 = ntile * N_CTA;

    const __half* Ag = g_encF + (size_t)m0 * NH;
    const __half* Bg = g_w2F + (size_t)n0 * NH;

    float c[4][8][4];
    #pragma unroll
    for (int i = 0; i < 4; i++)
        #pragma unroll
        for (int j = 0; j < 8; j++)
            #pragma unroll
            for (int k = 0; k < 4; k++) c[i][j][k] = 0.f;

    // prefetch chunk ci into stage st
    auto prefetch = [&](int ci, int st){
        const uint32_t so = sb + st * STAGESZ;
        const int k0 = ci * KCH;
        // A: 128 rows x 128B = 1024 x 16B units
        #pragma unroll
        for (int i = 0; i < 4; i++){
            int u = tid + i * 256;
            int row = u >> 3, cu = u & 7;
            uint32_t rel = (uint32_t)(row * 128) + (((uint32_t)cu * 16) ^ (((uint32_t)row & 7) << 4));
            cp16(so + rel, Ag + (size_t)row * NH + k0 + cu * 8);
        }
        // B: 256 rows x 128B = 2048 x 16B units
        #pragma unroll
        for (int i = 0; i < 8; i++){
            int u = tid + i * 256;
            int row = u >> 3, cu = u & 7;
            uint32_t rel = (uint32_t)(row * 128) + (((uint32_t)cu * 16) ^ (((uint32_t)row & 7) << 4));
            cp16(so + SB_OFF + rel, Bg + (size_t)row * NH + k0 + cu * 8);
        }
    };

    prefetch(0, 0); cp_commit();
    prefetch(1, 1); cp_commit();
    prefetch(2, 2); cp_commit();

    for (int ci = 0; ci < NCHUNK; ci++){
        cp_wait<2>();
        __syncthreads();
        const int st = ci % NSTAGE;
        const uint32_t so = sb + st * STAGESZ;
        #pragma unroll
        for (int ks = 0; ks < 4; ks++){
            const int r = lane & 15;
            const uint32_t colb = (uint32_t)(ks * 32 + (lane >> 4) * 16);
            uint32_t ah[4][4], bh[4][4];
            #pragma unroll
            for (int mf = 0; mf < 4; mf++){
                const uint32_t row = (uint32_t)(mbase + mf * 16 + r);
                const uint32_t rel = row * 128 + (colb ^ ((row & 7) << 4));
                ldsm4(ah[mf], so + rel);
            }
            #pragma unroll
            for (int nq = 0; nq < 4; nq++){
                const uint32_t row = (uint32_t)(nbase + nq * 16 + r);
                const uint32_t rel = row * 128 + (colb ^ ((row & 7) << 4));
                ldsm4(bh[nq], so + SB_OFF + rel);
            }
            #pragma unroll
            for (int mf = 0; mf < 4; mf++){
                #pragma unroll
                for (int nf = 0; nf < 8; nf++){
                    const int nq = nf >> 1, hi = nf & 1;
                    mma16816(c[mf][nf], ah[mf], bh[nq][hi], bh[nq][hi+2]);
                }
            }
        }
        __syncthreads();
        if (ci + NSTAGE < NCHUNK) prefetch(ci + NSTAGE, st);
        cp_commit();
    }

    // Epilogue: partial scores over this CTA's 256 n-cols.
    float rs0[4] = {0,0,0,0}, rs1[4] = {0,0,0,0};
    #pragma unroll
    for (int mf = 0; mf < 4; mf++){
        const int mlo = mbase + mf*16 + g;
        const int blo = mlo & 31;
        const int bhi = (mlo + 8) & 31;
        #pragma unroll
        for (int nf = 0; nf < 8; nf++){
            const int ngl = n0 + nbase + nf*8 + 2*t;
            float v0 = __ldg(&vW[ngl]), v1 = __ldg(&vW[ngl+1]);
            float h00 = g_hidc[blo*NH + ngl], h01 = g_hidc[blo*NH + ngl + 1];
            float h10 = g_hidc[bhi*NH + ngl], h11 = g_hidc[bhi*NH + ngl + 1];
            rs0[mf] += tanhf(c[mf][nf][0] + h00) * v0 + tanhf(c[mf][nf][1] + h01) * v1;
            rs1[mf] += tanhf(c[mf][nf][2] + h10) * v0 + tanhf(c[mf][nf][3] + h11) * v1;
        }
    }
    #pragma unroll
    for (int mf = 0; mf < 4; mf++){
        rs0[mf] += __shfl_xor_sync(0xffffffffu, rs0[mf], 1);
        rs0[mf] += __shfl_xor_sync(0xffffffffu, rs0[mf], 2);
        rs1[mf] += __shfl_xor_sync(0xffffffffu, rs1[mf], 1);
        rs1[mf] += __shfl_xor_sync(0xffffffffu, rs1[mf], 2);
    }
    __syncthreads();
    if (t == 0){
        #pragma unroll
        for (int mf = 0; mf < 4; mf++){
            s_row[mbase + mf*16 + g    ][wn] = rs0[mf];
            s_row[mbase + mf*16 + g + 8][wn] = rs1[mf];
        }
    }
    __syncthreads();
    if (tid < 128){
        float s = s_row[tid][0] + s_row[tid][1] + s_row[tid][2] + s_row[tid][3];
        g_part[(size_t)ntile * MTOT + m0 + tid] = s;
    }
}

// ---------------------------------------------------------------------------
// K3: sum partials -> softmax over S per batch -> attn_weights; zero ctx
// ---------------------------------------------------------------------------
__global__ void softmax_kernel(float* __restrict__ w_out, float* __restrict__ ctx){
    __shared__ float sc[NS];
    __shared__ float red[256];
    const int b = blockIdx.x, tid = threadIdx.x;

    #pragma unroll
    for (int i = tid; i < NH; i += 256) ctx[b * NH + i] = 0.f;

    float lmax = -1e30f;
    for (int s = tid; s < NS; s += 256){
        float v = 0.f;
        #pragma unroll
        for (int nt = 0; nt < NTILES; nt++)
            v += g_part[(size_t)nt * MTOT + s * NB + b];
        sc[s] = v;
        lmax = fmaxf(lmax, v);
    }
    red[tid] = lmax; __syncthreads();
    for (int o = 128; o > 0; o >>= 1){
        if (tid < o) red[tid] = fmaxf(red[tid], red[tid + o]);
        __syncthreads();
    }
    const float mx = red[0];
    __syncthreads();

    float lsum = 0.f;
    for (int s = tid; s < NS; s += 256){
        float e = expf(sc[s] - mx);
        sc[s] = e;
        lsum += e;
    }
    red[tid] = lsum; __syncthreads();
    for (int o = 128; o > 0; o >>= 1){
        if (tid < o) red[tid] = red[tid] + red[tid + o];
        __syncthreads();
    }
    const float inv = 1.f / red[0];
    for (int s = tid; s < NS; s += 256)
        w_out[b * NS + s] = sc[s] * inv;
}

// ---------------------------------------------------------------------------
// K4: context[b][h] += sum_{s in chunk} w[b][s] * enc[s][b][h]  (atomic)
// ---------------------------------------------------------------------------
__global__ void context_kernel(const float* __restrict__ enc,
                               const float* __restrict__ w,
                               float* __restrict__ ctx){
    const int b = blockIdx.y;
    const int h = blockIdx.x * 128 + threadIdx.x;
    const int s0 = blockIdx.z * 128;
    const float* e  = enc + (size_t)s0 * (NB*NH) + (size_t)b * NH + h;
    const float* wb = w + (size_t)b * NS + s0;
    float acc = 0.f;
    #pragma unroll 8
    for (int j = 0; j < 128; j++)
        acc += wb[j] * e[(size_t)j * (NB*NH)];
    atomicAdd(&ctx[(size_t)b * NH + h], acc);
}

// ---------------------------------------------------------------------------
extern "C" void kernel_launch(void* const* d_in, const int* in_sizes, int n_in,
                              void* d_out, int out_size){
    const float* hidden = (const float*)d_in[0];   // [B,H]
    const float* enc    = (const float*)d_in[1];   // [S,B,H]
    const float* attn_W = (const float*)d_in[2];   // [H,2H]
    const float* attn_b = (const float*)d_in[3];   // [H]
    const float* v_W    = (const float*)d_in[4];   // [1,H]
    float* out = (float*)d_out;
    float* ctx = out;                 // [B,H]
    float* wts = out + NB*NH;         // [B,S]

    cudaFuncSetAttribute(gemm_scores_mma, cudaFuncAttributeMaxDynamicSharedMemorySize, SMEM_TOTAL);

    cvt_enc_kernel<<<(MTOT*(NH/8))/256, 256>>>(enc);
    cvt_w2_kernel<<<(NH*(NH/8))/256, 256>>>(attn_W);
    hidc_kernel<<<128, 256>>>(hidden, attn_W, attn_b);
    gemm_scores_mma<<<dim3(NTILES, MTOT/M_CTA), 256, SMEM_TOTAL>>>(v_W);
    softmax_kernel<<<NB, 256>>>(wts, ctx);
    context_kernel<<<dim3(NH/128, NB, NS/128), 128>>>(enc, wts, ctx);
}